// round 15
// baseline (speedup 1.0000x reference)
#include <cuda_runtime.h>
#include <math.h>

#define NTOK 2048
#define NH   8
#define NN   32
#define NJ   34

#define SCALE0  0.25f
#define SCALE1  0.14433756729740643f
#define SHAREDC 0.70710678118654752f
#define NEGV    -1e9f

// ---------------- scratch ----------------
__device__ float g_skv0[NTOK * 256];       // [0..128)=k_self, [128..256)=v_self
__device__ float g_skv1[NTOK * 768];       // (i, o, m): o<128 k, o>=128 v
__device__ float g_out0[NTOK * 128];
__device__ float g_out1[NTOK * 384];       // (i, c, m)
__device__ float g_attn[NTOK * 288];       // RAW masked neighbor logits (j>=2), [NH][NJ]

__device__ __forceinline__ float dot4(float4 a, float4 b) {
    return a.x*b.x + a.y*b.y + a.z*b.z + a.w*b.w;
}

// ------- FFMA tiled SGEMM (C = A * B^T): 128 lanes, BM=32 x BN=32, BK=16 -------
#define BK  16
#define GLD 36

struct GemSm { float As[2][BK][GLD]; float Bs[2][BK][GLD]; };

template<int K>
__device__ __forceinline__ void gemm32(
    const float* __restrict__ A, const float* __restrict__ B, float* __restrict__ C,
    int lda, int eA, int ldc, int eC, int m0, int n0, int tl, GemSm* sm)
{
    const int tx = tl & 7;
    const int ty = tl >> 3;
    const int aK = tl & 15;
    const int aM = tl >> 4;

    float acc[2][4] = {};
    float ra[4], rb[4];

    #pragma unroll
    for (int r = 0; r < 4; r++) {
        ra[r] = A[(size_t)(m0 + aM + 8*r) * lda + (size_t)aK * eA];
        rb[r] = B[(size_t)(n0 + aM + 8*r) * K + aK];
    }

    int buf = 0;
    #pragma unroll
    for (int k0 = 0; k0 < K; k0 += BK) {
        #pragma unroll
        for (int r = 0; r < 4; r++) {
            sm->As[buf][aK][aM + 8*r] = ra[r];
            sm->Bs[buf][aK][aM + 8*r] = rb[r];
        }
        __syncthreads();
        const int kn = k0 + BK;
        if (kn < K) {
            #pragma unroll
            for (int r = 0; r < 4; r++) {
                ra[r] = A[(size_t)(m0 + aM + 8*r) * lda + (size_t)(kn + aK) * eA];
                rb[r] = B[(size_t)(n0 + aM + 8*r) * K + (kn + aK)];
            }
        }
        #pragma unroll
        for (int kk = 0; kk < BK; kk++) {
            float2 a = *(const float2*)&sm->As[buf][kk][ty * 2];
            float4 b = *(const float4*)&sm->Bs[buf][kk][tx * 4];
            float bv[4] = {b.x, b.y, b.z, b.w};
            #pragma unroll
            for (int s = 0; s < 4; s++) {
                acc[0][s] = fmaf(a.x, bv[s], acc[0][s]);
                acc[1][s] = fmaf(a.y, bv[s], acc[1][s]);
            }
        }
        buf ^= 1;
        if (kn < K) __syncthreads();
    }
    #pragma unroll
    for (int r = 0; r < 2; r++)
        #pragma unroll
        for (int s = 0; s < 4; s++)
            C[(size_t)(m0 + ty*2 + r) * ldc + (size_t)(n0 + tx*4 + s) * eC] = acc[r][s];
}

// ---------------- kernel 1: neighbor logits + FULL skv GEMM ride-along ----------------
// grid 3072 x 256 thr: bid%3==2 -> ride block (2 of 2048 skv tiles); else token.
struct LogSm {
    float q0s[128]; float q1s[384]; float wb[256];
    int wbin[4], wflt[4];
};
union USm { LogSm l; GemSm g[2]; };

__global__ __launch_bounds__(256) void logits_kernel(
    const float* __restrict__ q0, const float* __restrict__ q1,
    const float* __restrict__ k0, const float* __restrict__ k1,
    const float* __restrict__ edges, const float* __restrict__ wbias,
    const float* __restrict__ hw1, const void* __restrict__ nbmask,
    const float* __restrict__ feats0, const float* __restrict__ Wskv0,
    const float* __restrict__ feats1, const float* __restrict__ Wskv1)
{
    __shared__ __align__(16) USm sm;
    const int t = threadIdx.x;
    const int bid = blockIdx.x;
    const int rsel = bid % 3;

    if (rsel == 2) {
        // ---- skv GEMM tiles: 2048 tiles total (512 deg0 + 1536 deg1), 2 per block ----
        const int tile = 2 * (bid / 3) + (t >> 7);
        const int tl   = t & 127;
        GemSm* gs = &sm.g[t >> 7];
        if (tile < 512) {
            gemm32<128>(feats0, Wskv0, g_skv0, 128, 1, 256, 1,
                        (tile >> 3) * 32, (tile & 7) * 32, tl, gs);
        } else {
            const int tt = tile - 512;
            const int z = tt >> 9, rem = tt & 511;
            gemm32<64>(feats1 + z, Wskv1, g_skv1 + z, 192, 3, 768, 3,
                       (rem >> 3) * 32, (rem & 7) * 32, tl, gs);
        }
        return;
    }

    const int i = (bid / 3) * 2 + rsel;

    // ---- stage (+ mask-mode detect via warp ballots on warps 0..3) ----
    if (t < 128) {
        sm.l.q0s[t] = q0[(size_t)i * 128 + t] * (SCALE0 * SHAREDC);
        sm.l.wb[t]       = wbias[t] * SHAREDC;
        sm.l.wb[t + 128] = wbias[t + 128] * SHAREDC;
        unsigned wv = ((const unsigned*)nbmask)[t];
        int b = __all_sync(0xffffffffu, wv == 0u || wv == 1u);
        int f = __all_sync(0xffffffffu, wv == 0u || wv == 0x3F800000u);
        if ((t & 31) == 0) { sm.l.wbin[t >> 5] = b; sm.l.wflt[t >> 5] = f; }
    } else {
        int o = t - 128;
        #pragma unroll
        for (int rep = 0; rep < 3; rep++) {
            int oo = o + rep * 128;
            int h = oo / 48;
            float x = hw1[h];
            float sp = (x > 20.f) ? x : log1pf(__expf(x));
            sm.l.q1s[oo] = q1[(size_t)i * 384 + oo] * (sp * SCALE1 * SHAREDC);
        }
    }
    __syncthreads();

    const int mmode = (sm.l.wbin[0] & sm.l.wbin[1] & sm.l.wbin[2] & sm.l.wbin[3]) ? 1
                    : ((sm.l.wflt[0] & sm.l.wflt[1] & sm.l.wflt[2] & sm.l.wflt[3]) ? 2 : 0);

    // ---- neighbor logits: warp per j (8 warps x 4 its); raw masked -> g_attn ----
    {
        const int w = t >> 5, lane = t & 31;
        const int h = lane >> 2, part = lane & 3;
        const float4 qa = ((const float4*)sm.l.q0s)[lane];
        const float4* q1v = (const float4*)(sm.l.q1s + 12 * lane);
        const float4 qb0 = q1v[0], qb1 = q1v[1], qb2 = q1v[2];

        #pragma unroll 2
        for (int it = 0; it < 4; it++) {
            const int j = 2 + w + 8 * it;
            int valid = 1;
            if (part == 0) {
                int mi = i * NN + (j - 2);
                if (mmode == 1)      valid = ((const int*)nbmask)[mi] != 0;
                else if (mmode == 2) valid = ((const float*)nbmask)[mi] != 0.f;
                else                 valid = ((const unsigned char*)nbmask)[mi] != 0;
            }
            const size_t r = (size_t)i * NN + (j - 2);
            const float4* k0p = (const float4*)(k0 + r * 128);
            const float4* k1p = (const float4*)(k1 + r * 384 + 12 * lane);
            float4 ka  = k0p[lane];
            float4 kb0 = k1p[0], kb1 = k1p[1], kb2 = k1p[2];
            const float4* ep  = (const float4*)(edges + (size_t)i * 1024 + (j - 2) * 32 + part * 8);
            float4 e0 = ep[0], e1 = ep[1];
            const float4* wbp = (const float4*)(sm.l.wb + h * 32 + part * 8);
            float p = dot4(qa, ka) + dot4(qb0, kb0) + dot4(qb1, kb1) + dot4(qb2, kb2)
                    + dot4(e0, wbp[0]) + dot4(e1, wbp[1]);
            p += __shfl_down_sync(0xffffffffu, p, 2);
            p += __shfl_down_sync(0xffffffffu, p, 1);
            if (part == 0)
                g_attn[(size_t)i * 288 + h * NJ + j] = valid ? p : NEGV;
        }
    }
}

// --------- kernel 2: self/null logits + softmax + V accumulation ---------
__global__ __launch_bounds__(256) void fuse2_kernel(
    const float* __restrict__ q0, const float* __restrict__ q1,
    const float* __restrict__ v0, const float* __restrict__ v1,
    const float* __restrict__ nv0, const float* __restrict__ nv1,
    const float* __restrict__ nk0, const float* __restrict__ nk1,
    const float* __restrict__ hw1,
    const float* __restrict__ self_bias, const float* __restrict__ null_bias)
{
    const int i = blockIdx.x;
    const int t = threadIdx.x;

    __shared__ __align__(16) float q0s[128];
    __shared__ __align__(16) float q1s[384];
    __shared__ float totS[NH * NJ], attnS[NH * NJ];
    __shared__ float sbS[NH], nbS[NH];
    __shared__ __align__(16) float red[512];

    // ---- stage ----
    if (t < 128) {
        q0s[t] = q0[(size_t)i * 128 + t] * (SCALE0 * SHAREDC);
    } else {
        int o = t - 128;
        #pragma unroll
        for (int rep = 0; rep < 3; rep++) {
            int oo = o + rep * 128;
            int h = oo / 48;
            float x = hw1[h];
            float sp = (x > 20.f) ? x : log1pf(__expf(x));
            q1s[oo] = q1[(size_t)i * 384 + oo] * (sp * SCALE1 * SHAREDC);
        }
    }
    for (int l = t; l < NH * NJ; l += 256)
        totS[l] = g_attn[(size_t)i * 288 + l];
    if (t >= 168 && t < 176) {
        int h = t - 168;
        sbS[h] = self_bias[h] * SHAREDC;
        nbS[h] = null_bias[h] * SHAREDC;
    }
    __syncthreads();

    // ---- self (w==1) and null (w==0) logits ----
    {
        const int w = t >> 5, lane = t & 31;
        const int h = lane >> 2, part = lane & 3;
        if (w < 2) {
            const float4 qa = ((const float4*)q0s)[lane];
            const float4* q1v = (const float4*)(q1s + 12 * lane);
            const float* kp0 = (w == 0) ? nk0 : g_skv0 + (size_t)i * 256;
            const float* kp1 = (w == 0) ? nk1 : g_skv1 + (size_t)i * 768;
            float4 ka  = ((const float4*)kp0)[lane];
            const float4* k1p = (const float4*)(kp1 + 12 * lane);
            float4 kb0 = k1p[0], kb1 = k1p[1], kb2 = k1p[2];
            float p = dot4(qa, ka) + dot4(q1v[0], kb0) + dot4(q1v[1], kb1) + dot4(q1v[2], kb2);
            p += __shfl_down_sync(0xffffffffu, p, 2);
            p += __shfl_down_sync(0xffffffffu, p, 1);
            if (part == 0) {
                p += (w == 0) ? nbS[h] : sbS[h];
                totS[h * NJ + w] = p;
            }
        }
    }
    __syncthreads();

    // ---- softmax: warp w = head w over 34 logits ----
    {
        const int w = t >> 5, lane = t & 31;
        float x1 = totS[w * NJ + lane];
        float x2 = (lane < 2) ? totS[w * NJ + 32 + lane] : -2e9f;
        float mx = fmaxf(x1, x2);
        #pragma unroll
        for (int o = 16; o > 0; o >>= 1) mx = fmaxf(mx, __shfl_xor_sync(0xffffffffu, mx, o));
        float e1 = __expf(x1 - mx);
        float e2 = (lane < 2) ? __expf(x2 - mx) : 0.f;
        float s = e1 + e2;
        #pragma unroll
        for (int o = 16; o > 0; o >>= 1) s += __shfl_xor_sync(0xffffffffu, s, o);
        float inv = 1.f / s;
        attnS[w * NJ + lane] = e1 * inv;
        if (lane < 2) attnS[w * NJ + 32 + lane] = e2 * inv;
    }
    __syncthreads();

    // ---- V accumulation: 2 j-parity groups x 128 float4 slots, prefetch ----
    {
        const int g  = t >> 7;
        const int tl = t & 127;
        const bool isV1 = (tl < 96);
        const int off = isV1 ? 4 * tl : 4 * (tl - 96);
        const int hv  = isV1 ? (tl / 12) : ((tl - 96) / 4);
        const float* vb = isV1 ? v1 : v0;
        const int stride = isV1 ? 384 : 128;

        float4 acc = make_float4(0.f, 0.f, 0.f, 0.f);
        if (g == 0) {
            const float* np = (isV1 ? nv1 : nv0) + off;
            const float* sp = (isV1 ? g_skv1 + (size_t)i * 768 + 384
                                    : g_skv0 + (size_t)i * 256 + 128) + off;
            float4 vn = *(const float4*)np;
            float4 vs = *(const float4*)sp;
            float w0 = attnS[hv * NJ + 0], w1 = attnS[hv * NJ + 1];
            acc.x = w0 * vn.x + w1 * vs.x;
            acc.y = w0 * vn.y + w1 * vs.y;
            acc.z = w0 * vn.z + w1 * vs.z;
            acc.w = w0 * vn.w + w1 * vs.w;
        }
        const float* vrow = vb + ((size_t)i * NN + (g ? 16 : 0)) * stride + off;
        const int jbase = g ? 18 : 2;
        #pragma unroll
        for (int jj = 0; jj < 16; jj++) {
            float wgt = attnS[hv * NJ + jbase + jj];
            float4 v = *(const float4*)(vrow + (size_t)jj * stride);
            acc.x = fmaf(wgt, v.x, acc.x);
            acc.y = fmaf(wgt, v.y, acc.y);
            acc.z = fmaf(wgt, v.z, acc.z);
            acc.w = fmaf(wgt, v.w, acc.w);
        }
        if (g == 1) ((float4*)red)[tl] = acc;
        __syncthreads();
        if (g == 0) {
            float4 o = ((const float4*)red)[tl];
            acc.x += o.x; acc.y += o.y; acc.z += o.z; acc.w += o.w;
            if (isV1) *(float4*)(g_out1 + (size_t)i * 384 + off) = acc;
            else      *(float4*)(g_out0 + (size_t)i * 128 + off) = acc;
        }
    }
}

// ---------------- kernel 3: output projection (R13) ----------------
__global__ __launch_bounds__(128) void out_fused_kernel(
    const float* __restrict__ Wout0, const float* __restrict__ Wout1,
    float* __restrict__ out)
{
    if (blockIdx.z != 0 && blockIdx.x >= 2) return;
    __shared__ __align__(16) GemSm sm;
    const int m0 = blockIdx.y * 32, n0 = blockIdx.x * 32;
    if (blockIdx.z == 0) {
        gemm32<128>(g_out0, Wout0, out, 128, 1, 128, 1, m0, n0, threadIdx.x, &sm);
    } else {
        int m = blockIdx.z - 1;
        gemm32<128>(g_out1 + m, Wout1, out + (size_t)NTOK * 128 + m,
                    384, 3, 192, 3, m0, n0, threadIdx.x, &sm);
    }
}

// ---------------- launch ----------------
extern "C" void kernel_launch(void* const* d_in, const int* in_sizes, int n_in,
                              void* d_out, int out_size)
{
    const float* q0     = (const float*)d_in[0];
    const float* k0     = (const float*)d_in[1];
    const float* v0     = (const float*)d_in[2];
    const float* q1     = (const float*)d_in[3];
    const float* k1     = (const float*)d_in[4];
    const float* v1     = (const float*)d_in[5];
    const float* feats0 = (const float*)d_in[6];
    const float* feats1 = (const float*)d_in[7];
    const float* edges  = (const float*)d_in[8];
    const float* Wskv0  = (const float*)d_in[9];
    const float* Wskv1  = (const float*)d_in[10];
    const float* Wbias  = (const float*)d_in[11];
    const float* sbias  = (const float*)d_in[12];
    const float* nbias  = (const float*)d_in[13];
    const float* nk0    = (const float*)d_in[14];
    const float* nv0    = (const float*)d_in[15];
    const float* nk1    = (const float*)d_in[16];
    const float* nv1    = (const float*)d_in[17];
    const float* hw1    = (const float*)d_in[18];
    const float* Wout0  = (const float*)d_in[19];
    const float* Wout1  = (const float*)d_in[20];
    const void*  nbm    = d_in[21];
    float* out = (float*)d_out;

    // kernel 1: neighbor logits, with the FULL self-KV GEMM riding along (no predecessor)
    logits_kernel<<<3072, 256>>>(q0, q1, k0, k1, edges, Wbias, hw1, nbm,
                                 feats0, Wskv0, feats1, Wskv1);

    // kernel 2: self/null logits + softmax + V accumulation
    fuse2_kernel<<<NTOK, 256>>>(q0, q1, v0, v1, nv0, nv1, nk0, nk1, hw1,
                                sbias, nbias);

    // kernel 3: output projection
    out_fused_kernel<<<dim3(4, 64, 4), 128>>>(Wout0, Wout1, out);
}

// round 16
// speedup vs baseline: 1.1203x; 1.1203x over previous
#include <cuda_runtime.h>
#include <math.h>

#define NTOK 2048
#define NH   8
#define NN   32
#define NJ   34

#define SCALE0  0.25f
#define SCALE1  0.14433756729740643f
#define SHAREDC 0.70710678118654752f
#define NEGV    -1e9f

// ---------------- scratch ----------------
__device__ float g_skv0[NTOK * 256];       // [0..128)=k_self, [128..256)=v_self
__device__ float g_skv1[NTOK * 768];       // (i, o, m): o<128 k, o>=128 v
__device__ float g_out0[NTOK * 128];
__device__ float g_out1[NTOK * 384];       // (i, c, m)
__device__ float g_attn[NTOK * 288];       // per token: [NH][NJ] weights (272 used)
__device__ int   g_mask_mode;              // 0=byte, 1=int32, 2=float32

__device__ __forceinline__ float dot4(float4 a, float4 b) {
    return a.x*b.x + a.y*b.y + a.z*b.z + a.w*b.w;
}

// ------- FFMA tiled SGEMM (C = A * B^T), BM=32 x BN=32 -------
#define GLD 36

// BK=16 variant (used by the ride blocks inside logits; small smem keeps occupancy)
struct GemSm { float As[2][16][GLD]; float Bs[2][16][GLD]; };

template<int K>
__device__ __forceinline__ void gemm32(
    const float* __restrict__ A, const float* __restrict__ B, float* __restrict__ C,
    int lda, int eA, int ldc, int eC, int m0, int n0, int tl, GemSm* sm)
{
    const int tx = tl & 7;
    const int ty = tl >> 3;
    const int aK = tl & 15;
    const int aM = tl >> 4;

    float acc[2][4] = {};
    float ra[4], rb[4];

    #pragma unroll
    for (int r = 0; r < 4; r++) {
        ra[r] = A[(size_t)(m0 + aM + 8*r) * lda + (size_t)aK * eA];
        rb[r] = B[(size_t)(n0 + aM + 8*r) * K + aK];
    }

    int buf = 0;
    #pragma unroll
    for (int k0 = 0; k0 < K; k0 += 16) {
        #pragma unroll
        for (int r = 0; r < 4; r++) {
            sm->As[buf][aK][aM + 8*r] = ra[r];
            sm->Bs[buf][aK][aM + 8*r] = rb[r];
        }
        __syncthreads();
        const int kn = k0 + 16;
        if (kn < K) {
            #pragma unroll
            for (int r = 0; r < 4; r++) {
                ra[r] = A[(size_t)(m0 + aM + 8*r) * lda + (size_t)(kn + aK) * eA];
                rb[r] = B[(size_t)(n0 + aM + 8*r) * K + (kn + aK)];
            }
        }
        #pragma unroll
        for (int kk = 0; kk < 16; kk++) {
            float2 a = *(const float2*)&sm->As[buf][kk][ty * 2];
            float4 b = *(const float4*)&sm->Bs[buf][kk][tx * 4];
            float bv[4] = {b.x, b.y, b.z, b.w};
            #pragma unroll
            for (int s = 0; s < 4; s++) {
                acc[0][s] = fmaf(a.x, bv[s], acc[0][s]);
                acc[1][s] = fmaf(a.y, bv[s], acc[1][s]);
            }
        }
        buf ^= 1;
        if (kn < K) __syncthreads();
    }
    #pragma unroll
    for (int r = 0; r < 2; r++)
        #pragma unroll
        for (int s = 0; s < 4; s++)
            C[(size_t)(m0 + ty*2 + r) * ldc + (size_t)(n0 + tx*4 + s) * eC] = acc[r][s];
}

// BK=32 variant (standalone GEMM kernels; half the barriers)
struct GemSm32 { float As[2][32][GLD]; float Bs[2][32][GLD]; };

template<int K>
__device__ __forceinline__ void gemm32b(
    const float* __restrict__ A, const float* __restrict__ B, float* __restrict__ C,
    int lda, int eA, int ldc, int eC, int m0, int n0, int tl, GemSm32* sm)
{
    const int tx = tl & 7;
    const int ty = tl >> 3;
    const int aK = tl & 31;
    const int aM = tl >> 5;          // 0..3

    float acc[2][4] = {};
    float ra[8], rb[8];

    #pragma unroll
    for (int r = 0; r < 8; r++) {
        ra[r] = A[(size_t)(m0 + aM + 4*r) * lda + (size_t)aK * eA];
        rb[r] = B[(size_t)(n0 + aM + 4*r) * K + aK];
    }

    int buf = 0;
    #pragma unroll
    for (int k0 = 0; k0 < K; k0 += 32) {
        #pragma unroll
        for (int r = 0; r < 8; r++) {
            sm->As[buf][aK][aM + 4*r] = ra[r];
            sm->Bs[buf][aK][aM + 4*r] = rb[r];
        }
        __syncthreads();
        const int kn = k0 + 32;
        if (kn < K) {
            #pragma unroll
            for (int r = 0; r < 8; r++) {
                ra[r] = A[(size_t)(m0 + aM + 4*r) * lda + (size_t)(kn + aK) * eA];
                rb[r] = B[(size_t)(n0 + aM + 4*r) * K + (kn + aK)];
            }
        }
        #pragma unroll
        for (int kk = 0; kk < 32; kk++) {
            float2 a = *(const float2*)&sm->As[buf][kk][ty * 2];
            float4 b = *(const float4*)&sm->Bs[buf][kk][tx * 4];
            float bv[4] = {b.x, b.y, b.z, b.w};
            #pragma unroll
            for (int s = 0; s < 4; s++) {
                acc[0][s] = fmaf(a.x, bv[s], acc[0][s]);
                acc[1][s] = fmaf(a.y, bv[s], acc[1][s]);
            }
        }
        buf ^= 1;
        if (kn < K) __syncthreads();
    }
    #pragma unroll
    for (int r = 0; r < 2; r++)
        #pragma unroll
        for (int s = 0; s < 4; s++)
            C[(size_t)(m0 + ty*2 + r) * ldc + (size_t)(n0 + tx*4 + s) * eC] = acc[r][s];
}

// ---- self-K projection (+mask detect): 1D grid 1024, 128 thr ----
__global__ __launch_bounds__(128) void skv_k_kernel(
    const float* __restrict__ feats0, const float* __restrict__ Wskv0,
    const float* __restrict__ feats1, const float* __restrict__ Wskv1,
    const unsigned int* __restrict__ mask)
{
    if (blockIdx.x == 0 && threadIdx.x == 0) {
        int allBin = 1, allFloat = 1;
        for (int k = 0; k < 128; k++) {
            unsigned v = mask[k];
            if (v != 0u && v != 1u) allBin = 0;
            if (v != 0u && v != 0x3F800000u) allFloat = 0;
        }
        g_mask_mode = allBin ? 1 : (allFloat ? 2 : 0);
    }
    __shared__ __align__(16) GemSm32 sm;
    const int tile = blockIdx.x;            // 0..1023
    const int z = tile >> 8, rem = tile & 255;
    const int m0 = (rem >> 2) * 32, n0 = (rem & 3) * 32;   // K half: cols 0..127
    if (z == 0) {
        gemm32b<128>(feats0, Wskv0, g_skv0, 128, 1, 256, 1, m0, n0, threadIdx.x, &sm);
    } else {
        int m = z - 1;
        gemm32b<64>(feats1 + m, Wskv1, g_skv1 + m, 192, 3, 768, 3, m0, n0, threadIdx.x, &sm);
    }
}

// ---------------- output projection: compact 1D grid 640, 128 thr ----------------
__global__ __launch_bounds__(128) void out_fused_kernel(
    const float* __restrict__ Wout0, const float* __restrict__ Wout1,
    float* __restrict__ out)
{
    __shared__ __align__(16) GemSm32 sm;
    const int tile = blockIdx.x;            // 0..639
    if (tile < 256) {
        const int m0 = (tile >> 2) * 32, n0 = (tile & 3) * 32;
        gemm32b<128>(g_out0, Wout0, out, 128, 1, 128, 1, m0, n0, threadIdx.x, &sm);
    } else {
        const int tt = tile - 256;
        const int m = tt / 128, rem = tt % 128;
        const int m0 = (rem >> 1) * 32, n0 = (rem & 1) * 32;
        gemm32b<128>(g_out1 + m, Wout1, out + (size_t)NTOK * 128 + m,
                     384, 3, 192, 3, m0, n0, threadIdx.x, &sm);
    }
}

// ---------------- logits + softmax + ride-along self-V GEMM (R13) ----------------
#define RIDE_BLOCKS 512

struct LogSm {
    float q0s[128]; float q1s[384]; float wb[256];
    float sbS[NH], nbS[NH];
    float totS[NH * NJ]; float attnS[NH * NJ];
    int validS[NJ];
};
union USm { LogSm l; GemSm g[2]; };

__global__ __launch_bounds__(256) void logits_kernel(
    const float* __restrict__ q0, const float* __restrict__ q1,
    const float* __restrict__ k0, const float* __restrict__ k1,
    const float* __restrict__ edges, const float* __restrict__ wbias,
    const float* __restrict__ self_bias, const float* __restrict__ null_bias,
    const float* __restrict__ nk0, const float* __restrict__ nk1,
    const float* __restrict__ hw1, const void* __restrict__ nbmask,
    const float* __restrict__ feats0, const float* __restrict__ Wskv0,
    const float* __restrict__ feats1, const float* __restrict__ Wskv1)
{
    __shared__ __align__(16) USm sm;
    const int t = threadIdx.x;

    if (blockIdx.x < RIDE_BLOCKS) {
        const int tile = 2 * blockIdx.x + (t >> 7);
        const int tl   = t & 127;
        const int z    = tile >> 8;
        const int rem  = tile & 255;
        const int y    = rem >> 2, x = rem & 3;
        const int m0 = 32 * y, n0 = 128 + 32 * x;
        GemSm* gs = &sm.g[t >> 7];
        if (z == 0) {
            gemm32<128>(feats0, Wskv0, g_skv0, 128, 1, 256, 1, m0, n0, tl, gs);
        } else {
            int m = z - 1;
            gemm32<64>(feats1 + m, Wskv1, g_skv1 + m, 192, 3, 768, 3, m0, n0, tl, gs);
        }
        return;
    }

    const int i = blockIdx.x - RIDE_BLOCKS;

    // ---- stage ----
    if (t < 128) {
        sm.l.q0s[t] = q0[(size_t)i * 128 + t] * (SCALE0 * SHAREDC);
        sm.l.wb[t]       = wbias[t] * SHAREDC;
        sm.l.wb[t + 128] = wbias[t + 128] * SHAREDC;
    } else {
        int o = t - 128;
        #pragma unroll
        for (int rep = 0; rep < 3; rep++) {
            int oo = o + rep * 128;
            int h = oo / 48;
            float x = hw1[h];
            float sp = (x > 20.f) ? x : log1pf(__expf(x));
            sm.l.q1s[oo] = q1[(size_t)i * 384 + oo] * (sp * SCALE1 * SHAREDC);
        }
    }
    if (t >= 128 && t < 128 + NJ) {
        int j = t - 128;
        if (j < 2) {
            sm.l.validS[j] = 1;
        } else {
            int mm = g_mask_mode;
            int mi = i * NN + (j - 2);
            int valid;
            if (mm == 1)      valid = ((const int*)nbmask)[mi] != 0;
            else if (mm == 2) valid = ((const float*)nbmask)[mi] != 0.f;
            else              valid = ((const unsigned char*)nbmask)[mi] != 0;
            sm.l.validS[j] = valid;
        }
    }
    if (t >= 168 && t < 176) {
        int h = t - 168;
        sm.l.sbS[h] = self_bias[h] * SHAREDC;
        sm.l.nbS[h] = null_bias[h] * SHAREDC;
    }
    __syncthreads();

    // ---- logits: warp per j; compile-time unrolled ----
    {
        const int w = t >> 5, lane = t & 31;
        const int h = lane >> 2, part = lane & 3;
        const float4 qa = ((const float4*)sm.l.q0s)[lane];
        const float4* q1v = (const float4*)(sm.l.q1s + 12 * lane);
        const float4 qb0 = q1v[0], qb1 = q1v[1], qb2 = q1v[2];

        #pragma unroll 2
        for (int it = 0; it < 4; it++) {
            const int j = 2 + w + 8 * it;
            const size_t r = (size_t)i * NN + (j - 2);
            const float4* k0p = (const float4*)(k0 + r * 128);
            const float4* k1p = (const float4*)(k1 + r * 384 + 12 * lane);
            float4 ka  = k0p[lane];
            float4 kb0 = k1p[0], kb1 = k1p[1], kb2 = k1p[2];
            const float4* ep  = (const float4*)(edges + (size_t)i * 1024 + (j - 2) * 32 + part * 8);
            float4 e0 = ep[0], e1 = ep[1];
            const float4* wbp = (const float4*)(sm.l.wb + h * 32 + part * 8);
            float p = dot4(qa, ka) + dot4(qb0, kb0) + dot4(qb1, kb1) + dot4(qb2, kb2)
                    + dot4(e0, wbp[0]) + dot4(e1, wbp[1]);
            p += __shfl_down_sync(0xffffffffu, p, 2);
            p += __shfl_down_sync(0xffffffffu, p, 1);
            if (part == 0)
                sm.l.totS[h * NJ + j] = sm.l.validS[j] ? p : NEGV;
        }

        if (w < 2) {
            const float* kp0 = (w == 0) ? nk0 : g_skv0 + (size_t)i * 256;
            const float* kp1 = (w == 0) ? nk1 : g_skv1 + (size_t)i * 768;
            float4 ka  = ((const float4*)kp0)[lane];
            const float4* k1p = (const float4*)(kp1 + 12 * lane);
            float4 kb0 = k1p[0], kb1 = k1p[1], kb2 = k1p[2];
            float p = dot4(qa, ka) + dot4(qb0, kb0) + dot4(qb1, kb1) + dot4(qb2, kb2);
            p += __shfl_down_sync(0xffffffffu, p, 2);
            p += __shfl_down_sync(0xffffffffu, p, 1);
            if (part == 0) {
                p += (w == 0) ? sm.l.nbS[h] : sm.l.sbS[h];
                sm.l.totS[h * NJ + w] = p;
            }
        }
    }
    __syncthreads();

    // ---- softmax: warp w = head w ----
    {
        const int w = t >> 5, lane = t & 31;
        float x1 = sm.l.totS[w * NJ + lane];
        float x2 = (lane < 2) ? sm.l.totS[w * NJ + 32 + lane] : -2e9f;
        float mx = fmaxf(x1, x2);
        #pragma unroll
        for (int o = 16; o > 0; o >>= 1) mx = fmaxf(mx, __shfl_xor_sync(0xffffffffu, mx, o));
        float e1 = __expf(x1 - mx);
        float e2 = (lane < 2) ? __expf(x2 - mx) : 0.f;
        float s = e1 + e2;
        #pragma unroll
        for (int o = 16; o > 0; o >>= 1) s += __shfl_xor_sync(0xffffffffu, s, o);
        float inv = 1.f / s;
        sm.l.attnS[w * NJ + lane] = e1 * inv;
        if (lane < 2) sm.l.attnS[w * NJ + 32 + lane] = e2 * inv;
    }
    __syncthreads();
    for (int l = t; l < NH * NJ; l += 256)
        g_attn[(size_t)i * 288 + l] = sm.l.attnS[l];
}

// ---------------- V accumulation: one token per 256-thread block (R13) ----------------
__global__ __launch_bounds__(256) void vaccum_kernel(
    const float* __restrict__ v0, const float* __restrict__ v1,
    const float* __restrict__ nv0, const float* __restrict__ nv1)
{
    const int i = blockIdx.x;
    const int t = threadIdx.x;

    __shared__ float aS[NH * NJ];
    __shared__ __align__(16) float red[512];

    for (int l = t; l < NH * NJ; l += 256)
        aS[l] = g_attn[(size_t)i * 288 + l];
    __syncthreads();

    const int g  = t >> 7;
    const int tl = t & 127;
    const bool isV1 = (tl < 96);
    const int off = isV1 ? 4 * tl : 4 * (tl - 96);
    const int hv  = isV1 ? (tl / 12) : ((tl - 96) / 4);
    const float* vb = isV1 ? v1 : v0;
    const int stride = isV1 ? 384 : 128;

    float4 acc = make_float4(0.f, 0.f, 0.f, 0.f);
    if (g == 0) {
        const float* np = (isV1 ? nv1 : nv0) + off;
        const float* sp = (isV1 ? g_skv1 + (size_t)i * 768 + 384
                                : g_skv0 + (size_t)i * 256 + 128) + off;
        float4 vn = *(const float4*)np;
        float4 vs = *(const float4*)sp;
        float w0 = aS[hv * NJ + 0], w1 = aS[hv * NJ + 1];
        acc.x = w0 * vn.x + w1 * vs.x;
        acc.y = w0 * vn.y + w1 * vs.y;
        acc.z = w0 * vn.z + w1 * vs.z;
        acc.w = w0 * vn.w + w1 * vs.w;
    }
    const float* vrow = vb + ((size_t)i * NN + (g ? 16 : 0)) * stride + off;
    const int jbase = g ? 18 : 2;
    #pragma unroll
    for (int jj = 0; jj < 16; jj++) {
        float wgt = aS[hv * NJ + jbase + jj];
        float4 v = *(const float4*)(vrow + (size_t)jj * stride);
        acc.x = fmaf(wgt, v.x, acc.x);
        acc.y = fmaf(wgt, v.y, acc.y);
        acc.z = fmaf(wgt, v.z, acc.z);
        acc.w = fmaf(wgt, v.w, acc.w);
    }
    if (g == 1) ((float4*)red)[tl] = acc;
    __syncthreads();
    if (g == 0) {
        float4 o = ((const float4*)red)[tl];
        acc.x += o.x; acc.y += o.y; acc.z += o.z; acc.w += o.w;
        if (isV1) *(float4*)(g_out1 + (size_t)i * 384 + off) = acc;
        else      *(float4*)(g_out0 + (size_t)i * 128 + off) = acc;
    }
}

// ---------------- launch ----------------
extern "C" void kernel_launch(void* const* d_in, const int* in_sizes, int n_in,
                              void* d_out, int out_size)
{
    const float* q0     = (const float*)d_in[0];
    const float* k0     = (const float*)d_in[1];
    const float* v0     = (const float*)d_in[2];
    const float* q1     = (const float*)d_in[3];
    const float* k1     = (const float*)d_in[4];
    const float* v1     = (const float*)d_in[5];
    const float* feats0 = (const float*)d_in[6];
    const float* feats1 = (const float*)d_in[7];
    const float* edges  = (const float*)d_in[8];
    const float* Wskv0  = (const float*)d_in[9];
    const float* Wskv1  = (const float*)d_in[10];
    const float* Wbias  = (const float*)d_in[11];
    const float* sbias  = (const float*)d_in[12];
    const float* nbias  = (const float*)d_in[13];
    const float* nk0    = (const float*)d_in[14];
    const float* nv0    = (const float*)d_in[15];
    const float* nk1    = (const float*)d_in[16];
    const float* nv1    = (const float*)d_in[17];
    const float* hw1    = (const float*)d_in[18];
    const float* Wout0  = (const float*)d_in[19];
    const float* Wout1  = (const float*)d_in[20];
    const void*  nbm    = d_in[21];
    float* out = (float*)d_out;

    // self-K projection (half the skv GEMM) + mask detect
    skv_k_kernel<<<1024, 128>>>(
        feats0, Wskv0, feats1, Wskv1, (const unsigned int*)nbm);

    // logits + softmax, with self-V GEMM tiles riding along as the first 512 blocks
    logits_kernel<<<RIDE_BLOCKS + NTOK, 256>>>(
        q0, q1, k0, k1, edges, Wbias, sbias, nbias, nk0, nk1, hw1, nbm,
        feats0, Wskv0, feats1, Wskv1);

    vaccum_kernel<<<NTOK, 256>>>(v0, v1, nv0, nv1);

    out_fused_kernel<<<640, 128>>>(Wout0, Wout1, out);
}